// round 1
// baseline (speedup 1.0000x reference)
#include <cuda_runtime.h>
#include <cstdint>

// ---------------- problem constants (fixed by dataset) ----------------
#define NPC     8            // nodes per CTA
#define DEG     16           // in-degree
#define EPC     128          // edges per CTA = NPC*DEG
#define HID     128          // hidden = msg = 128
#define THREADS 256

// ---------------- smem layout (float offsets) ----------------
#define XS  264              // X stride (257 cols padded, 16B-aligned rows)
#define MS  132              // matrix stride for 128-col tiles

#define OFF_X    0           // 128*264 = 33792   (X; later reused as A0/A1)
#define OFF_A0   0           // 128*132
#define OFF_A1   16896       // 128*132
#define OFF_B    33792       // 128*132 = 16896
#define OFF_W    50688       // 16*128 = 2048 weight staging
#define OFF_HD   52736       // 8*132 = 1056 hidden[dst]
#define OFF_MI   53792       // 8*132 = 1056 m_i
#define OFF_DIF  54848       // 128*3
#define OFF_L2   55232       // 128
#define OFF_G    55360       // 128
#define OFF_C    55488       // 128
#define OFF_WA   55616       // 128
#define OFF_WC2  55744       // 128
#define OFF_INT  55872       // ints: src[128], dst[128], dstN[8]
#define SMEM_FLOATS 56136
#define SMEM_BYTES  (SMEM_FLOATS * 4)

typedef unsigned long long u64;

// ---------------- fast packed / transcendental helpers ----------------
__device__ __forceinline__ u64 pack2(float lo, float hi) {
    u64 r; asm("mov.b64 %0, {%1, %2};" : "=l"(r) : "f"(lo), "f"(hi)); return r;
}
__device__ __forceinline__ void unpack2(u64 v, float& lo, float& hi) {
    asm("mov.b64 {%0, %1}, %2;" : "=f"(lo), "=f"(hi) : "l"(v));
}
// packed dual fp32 FMA (Blackwell FFMA2): d = a*b + d  (elementwise on pairs)
#define FMA2(d, a, b) asm("fma.rn.f32x2 %0, %1, %2, %0;" : "+l"(d) : "l"(a), "l"(b))

__device__ __forceinline__ float fast_tanh(float x) {
    // tanh(x) = 1 - 2/(1+exp(2x)); exact at +-inf saturation
    float z; asm("ex2.approx.f32 %0, %1;" : "=f"(z) : "f"(2.8853900817779268f * x));
    float r; asm("rcp.approx.f32 %0, %1;" : "=f"(r) : "f"(1.0f + z));
    return __fmaf_rn(-2.0f, r, 1.0f);
}
__device__ __forceinline__ float fast_sigmoid(float x) {
    float z; asm("ex2.approx.f32 %0, %1;" : "=f"(z) : "f"(-1.4426950408889634f * x));
    float r; asm("rcp.approx.f32 %0, %1;" : "=f"(r) : "f"(1.0f + z));
    return r;
}

// ---------------- 128x128 register-tiled GEMM (f32x2 FMA) ----------------
// dst[128][MS] = tanh( src[128][sstride] (:,0:K) @ Wg[K(+1)][128] + bias
//                      (+ extraX[row] * Wg[K][:] if extraX) )
// thread (ty,tx): rows ty*8+i, col pairs {4*tx + 64*q + 2h, +1}
__device__ __forceinline__ void gemm_tile(
    float* sm, const float* src, int sstride, int K,
    const float* __restrict__ Wg, const float* __restrict__ bias,
    const float* extraX, float* dst, int tid)
{
    const int tx = tid & 15, ty = tid >> 4;
    float* sW = sm + OFF_W;

    u64 acc[8][4];
    {
        u64 bp[4];
        #pragma unroll
        for (int q = 0; q < 2; q++) {
            const u64* bb = (const u64*)(bias + 4 * tx + 64 * q);
            bp[2 * q] = bb[0]; bp[2 * q + 1] = bb[1];
        }
        #pragma unroll
        for (int i = 0; i < 8; i++)
            #pragma unroll
            for (int p = 0; p < 4; p++) acc[i][p] = bp[p];
    }

    for (int kc = 0; kc < K; kc += 16) {
        __syncthreads();
        #pragma unroll
        for (int v = 0; v < 2; v++) {
            int idx = tid * 8 + v * 4;
            *(float4*)(sW + idx) =
                *(const float4*)(Wg + (kc + (idx >> 7)) * HID + (idx & 127));
        }
        __syncthreads();
        #pragma unroll
        for (int kk = 0; kk < 16; kk++) {
            u64 xp[8];
            #pragma unroll
            for (int i = 0; i < 8; i++) {
                float xv = src[(ty * 8 + i) * sstride + kc + kk];
                xp[i] = pack2(xv, xv);
            }
            u64 wp[4];
            #pragma unroll
            for (int q = 0; q < 2; q++) {
                const u64* ws = (const u64*)(sW + kk * HID + 4 * tx + 64 * q);
                wp[2 * q] = ws[0]; wp[2 * q + 1] = ws[1];
            }
            #pragma unroll
            for (int i = 0; i < 8; i++)
                #pragma unroll
                for (int p = 0; p < 4; p++) FMA2(acc[i][p], xp[i], wp[p]);
        }
    }

    if (extraX) {  // rank-1 term: column K of Wg times per-row scalar (the l2 column)
        u64 wl[4];
        #pragma unroll
        for (int q = 0; q < 2; q++) {
            const u64* ws = (const u64*)(Wg + K * HID + 4 * tx + 64 * q);
            wl[2 * q] = ws[0]; wl[2 * q + 1] = ws[1];
        }
        #pragma unroll
        for (int i = 0; i < 8; i++) {
            float xv = extraX[ty * 8 + i];
            u64 xp = pack2(xv, xv);
            #pragma unroll
            for (int p = 0; p < 4; p++) FMA2(acc[i][p], xp, wl[p]);
        }
    }

    #pragma unroll
    for (int i = 0; i < 8; i++) {
        int row = ty * 8 + i;
        #pragma unroll
        for (int q = 0; q < 2; q++) {
            float a, b, c, d;
            unpack2(acc[i][2 * q], a, b);
            unpack2(acc[i][2 * q + 1], c, d);
            float4 o;
            o.x = fast_tanh(a); o.y = fast_tanh(b);
            o.z = fast_tanh(c); o.w = fast_tanh(d);
            *(float4*)(dst + row * MS + 4 * tx + 64 * q) = o;
        }
    }
}

// ---------------- fused EGNN layer kernel ----------------
__global__ void __launch_bounds__(THREADS, 1)
egnn_kernel(const float* __restrict__ coords, const float* __restrict__ hidden,
            const void*  __restrict__ edges,
            const float* __restrict__ W1,  const float* __restrict__ b1,
            const float* __restrict__ W2,  const float* __restrict__ b2,
            const float* __restrict__ Wa,  const float* __restrict__ ba,
            const float* __restrict__ Wc1, const float* __restrict__ bc1,
            const float* __restrict__ Wc2,
            const float* __restrict__ Wh1, const float* __restrict__ bh1,
            const float* __restrict__ Wh2, const float* __restrict__ bh2,
            float* __restrict__ out, int N)
{
    extern __shared__ float sm[];
    int* smi   = (int*)(sm + OFF_INT);
    int* sSrc  = smi;
    int* sDst  = smi + 128;
    int* sDstN = smi + 256;

    const int tid   = threadIdx.x;
    const int E     = N * DEG;
    const int ebase = blockIdx.x * EPC;

    // edges dtype: jax may emit int32 (x64 disabled) or int64. For this graph
    // src[0]=1, src[1]=2: int64 little-endian has zero high words at odd int32 slots.
    const int*       e32 = (const int*)edges;
    const long long* e64 = (const long long*)edges;
    const bool is64 = (e32[1] == 0) && (e32[3] == 0);

    // ---- phase 1a: per-edge scalars + small weight vectors ----
    if (tid < EPC) {
        int e = ebase + tid;
        int s, d;
        if (is64) { s = (int)e64[e]; d = (int)e64[E + e]; }
        else      { s = e32[e];      d = e32[E + e]; }
        sSrc[tid] = s; sDst[tid] = d;
        float dx = coords[s * 3 + 0] - coords[d * 3 + 0];
        float dy = coords[s * 3 + 1] - coords[d * 3 + 1];
        float dz = coords[s * 3 + 2] - coords[d * 3 + 2];
        sm[OFF_DIF + tid * 3 + 0] = dx;
        sm[OFF_DIF + tid * 3 + 1] = dy;
        sm[OFF_DIF + tid * 3 + 2] = dz;
        sm[OFF_L2 + tid] = sqrtf(dx * dx + dy * dy + dz * dz);
    } else {
        int t = tid - 128;
        sm[OFF_WA  + t] = Wa[t];
        sm[OFF_WC2 + t] = Wc2[t];
    }
    __syncthreads();

    // ---- phase 1b: build X = [h_src | h_dst | l2], record dst node ids ----
    if (tid < NPC) sDstN[tid] = sDst[tid * DEG];
    {
        int w = tid >> 5, lane = tid & 31;
        #pragma unroll
        for (int r = 0; r < 16; r++) {
            int e = w * 16 + r;
            const float4* hs = (const float4*)(hidden + sSrc[e] * HID) + lane;
            const float4* hd = (const float4*)(hidden + sDst[e] * HID) + lane;
            *(float4*)(sm + OFF_X + e * XS + 4 * lane)        = *hs;
            *(float4*)(sm + OFF_X + e * XS + HID + 4 * lane)  = *hd;
        }
    }
    if (tid < EPC) sm[OFF_X + tid * XS + 256] = sm[OFF_L2 + tid];
    __syncthreads();

    // ---- phase 1c: stage hidden[dst] rows for the node MLP ----
    {
        int idx = tid * 4;                  // 1024 floats total
        int n = idx >> 7, c = idx & 127;
        *(float4*)(sm + OFF_HD + n * MS + c) =
            *(const float4*)(hidden + sDstN[n] * HID + c);
    }
    __syncthreads();

    // ---- m1 = tanh(X @ W1 + b1)  (K=256 + l2 rank-1 column) ----
    gemm_tile(sm, sm + OFF_X, XS, 256, W1, b1, sm + OFF_L2, sm + OFF_B, tid);
    __syncthreads();
    // ---- m2 = tanh(m1 @ W2 + b2) ----
    gemm_tile(sm, sm + OFF_B, MS, 128, W2, b2, nullptr, sm + OFF_A0, tid);
    __syncthreads();

    // ---- attention gate: g = sigmoid(m2 . Wa + ba); m = g * m2 (in place) ----
    if (tid < EPC) {
        float s = ba[0];
        const float* row = sm + OFF_A0 + tid * MS;
        #pragma unroll 8
        for (int k = 0; k < 128; k++) s = __fmaf_rn(row[k], sm[OFF_WA + k], s);
        sm[OFF_G + tid] = fast_sigmoid(s);
    }
    __syncthreads();
    {
        int e = tid & 127, j0 = (tid >> 7) * 64;
        float g = sm[OFF_G + e];
        float* row = sm + OFF_A0 + e * MS + j0;
        #pragma unroll
        for (int j = 0; j < 64; j++) row[j] *= g;
    }
    __syncthreads();

    // ---- mc = tanh(m @ Wc1 + bc1) ----
    gemm_tile(sm, sm + OFF_A0, MS, 128, Wc1, bc1, nullptr, sm + OFF_A1, tid);
    __syncthreads();

    // ---- c = tanh(mc . Wc2); m_i = segment-sum of m over the 16 edges ----
    if (tid < EPC) {
        float s = 0.f;
        const float* row = sm + OFF_A1 + tid * MS;
        #pragma unroll 8
        for (int k = 0; k < 128; k++) s = __fmaf_rn(row[k], sm[OFF_WC2 + k], s);
        sm[OFF_C + tid] = fast_tanh(s);
    }
    {
        int j = tid & 127, ng = tid >> 7;
        #pragma unroll
        for (int i = 0; i < 4; i++) {
            int n = ng * 4 + i;
            float s = 0.f;
            const float* base = sm + OFF_A0 + (n * DEG) * MS + j;
            #pragma unroll
            for (int d = 0; d < DEG; d++) s += base[d * MS];
            sm[OFF_MI + n * MS + j] = s;
        }
    }
    __syncthreads();

    // ---- coords_out = coords + (sum_e c_e * dif_e) / indeg ----
    if (tid < NPC * 3) {
        int n = tid / 3, d = tid - n * 3;
        float s = 0.f;
        #pragma unroll
        for (int k = 0; k < DEG; k++)
            s = __fmaf_rn(sm[OFF_C + n * DEG + k],
                          sm[OFF_DIF + (n * DEG + k) * 3 + d], s);
        int node = sDstN[n];
        out[node * 3 + d] = coords[node * 3 + d] + s * (1.0f / DEG);
    }

    // ---- node MLP part 1: th = tanh([h_dst | m_i] @ Wh1 + bh1) -> sB ----
    {
        int j = tid & 127, ng = tid >> 7;
        float acc[4];
        float bb = bh1[j];
        #pragma unroll
        for (int i = 0; i < 4; i++) acc[i] = bb;
        float* sW = sm + OFF_W;
        for (int kc = 0; kc < 256; kc += 16) {
            __syncthreads();
            #pragma unroll
            for (int v = 0; v < 2; v++) {
                int idx = tid * 8 + v * 4;
                *(float4*)(sW + idx) =
                    *(const float4*)(Wh1 + (kc + (idx >> 7)) * HID + (idx & 127));
            }
            __syncthreads();
            const float* xb = (kc < 128) ? (sm + OFF_HD + kc) : (sm + OFF_MI + (kc - 128));
            #pragma unroll
            for (int kk = 0; kk < 16; kk++) {
                float w = sW[kk * HID + j];
                #pragma unroll
                for (int i = 0; i < 4; i++)
                    acc[i] = __fmaf_rn(xb[(ng * 4 + i) * MS + kk], w, acc[i]);
            }
        }
        #pragma unroll
        for (int i = 0; i < 4; i++)
            sm[OFF_B + (ng * 4 + i) * MS + j] = fast_tanh(acc[i]);
    }
    __syncthreads();

    // ---- node MLP part 2: hidden_out = hidden + th @ Wh2 + bh2 ----
    {
        int j = tid & 127, ng = tid >> 7;
        float acc[4];
        float bb = bh2[j];
        #pragma unroll
        for (int i = 0; i < 4; i++) acc[i] = bb;
        float* sW = sm + OFF_W;
        for (int kc = 0; kc < 128; kc += 16) {
            __syncthreads();
            #pragma unroll
            for (int v = 0; v < 2; v++) {
                int idx = tid * 8 + v * 4;
                *(float4*)(sW + idx) =
                    *(const float4*)(Wh2 + (kc + (idx >> 7)) * HID + (idx & 127));
            }
            __syncthreads();
            #pragma unroll
            for (int kk = 0; kk < 16; kk++) {
                float w = sW[kk * HID + j];
                #pragma unroll
                for (int i = 0; i < 4; i++)
                    acc[i] = __fmaf_rn(sm[OFF_B + (ng * 4 + i) * MS + kc + kk], w, acc[i]);
            }
        }
        float* oh = out + N * 3;
        #pragma unroll
        for (int i = 0; i < 4; i++) {
            int n = ng * 4 + i;
            oh[sDstN[n] * HID + j] = sm[OFF_HD + n * MS + j] + acc[i];
        }
    }
}

// ---------------- launch ----------------
extern "C" void kernel_launch(void* const* d_in, const int* in_sizes, int n_in,
                              void* d_out, int out_size)
{
    const float* coords = (const float*)d_in[0];
    const float* hidden = (const float*)d_in[1];
    const void*  edges  = d_in[2];
    const float* W1  = (const float*)d_in[3];
    const float* b1  = (const float*)d_in[4];
    const float* W2  = (const float*)d_in[5];
    const float* b2  = (const float*)d_in[6];
    const float* Wa  = (const float*)d_in[7];
    const float* ba  = (const float*)d_in[8];
    const float* Wc1 = (const float*)d_in[9];
    const float* bc1 = (const float*)d_in[10];
    const float* Wc2 = (const float*)d_in[11];
    const float* Wh1 = (const float*)d_in[12];
    const float* bh1 = (const float*)d_in[13];
    const float* Wh2 = (const float*)d_in[14];
    const float* bh2 = (const float*)d_in[15];

    int N = in_sizes[0] / 3;          // coords is [N,3]
    float* out = (float*)d_out;       // [N*3 coords_out][N*128 hidden_out]

    cudaFuncSetAttribute(egnn_kernel, cudaFuncAttributeMaxDynamicSharedMemorySize,
                         SMEM_BYTES);
    egnn_kernel<<<N / NPC, THREADS, SMEM_BYTES>>>(
        coords, hidden, edges, W1, b1, W2, b2, Wa, ba, Wc1, bc1, Wc2,
        Wh1, bh1, Wh2, bh2, out, N);
}

// round 9
// speedup vs baseline: 1.1070x; 1.1070x over previous
#include <cuda_runtime.h>
#include <cstdint>

// ---------------- problem constants ----------------
#define NPC     8            // nodes per CTA
#define DEG     16
#define EPC     128          // edges per CTA
#define HID     128
#define THREADS 512

#define MS  132              // row stride for 128-col tiles (16B aligned)

// ---------------- smem layout (float offsets) ----------------
#define OFF_XA   0           // 128*132 = 16896  (h_src; later A0 = gated m)
#define OFF_B    16896       // 128*132          (m1; later A1 = mc)
#define OFF_W    33792       // 2 * 32*128 = 8192 (double-buffered weight chunks)
#define OFF_HD   41984       // 8*132  raw hidden[dst]
#define OFF_HD1  43040       // 8*132  h_dst @ W1[128:256] + b1
#define OFF_MI   44096       // 8*132  m_i
#define OFF_TH   45152       // 8*132  node-MLP hidden
#define OFF_DIF  46208       // 128*3
#define OFF_L2   46592       // 128
#define OFF_C    46720       // 128
#define OFF_WL2  46848       // 128 (W1 row 256)
#define OFF_WA   46976       // 128
#define OFF_WC2  47104       // 128
#define OFF_INT  47232       // ints: src[128], dst[128], dstN[8]
#define SMEM_FLOATS 47500
#define SMEM_BYTES  (SMEM_FLOATS * 4)

typedef unsigned long long u64;

// ---------------- helpers ----------------
__device__ __forceinline__ u64 pack2(float lo, float hi) {
    u64 r; asm("mov.b64 %0, {%1, %2};" : "=l"(r) : "f"(lo), "f"(hi)); return r;
}
__device__ __forceinline__ void unpack2(u64 v, float& lo, float& hi) {
    asm("mov.b64 {%0, %1}, %2;" : "=f"(lo), "=f"(hi) : "l"(v));
}
#define FMA2(d, a, b) asm("fma.rn.f32x2 %0, %1, %2, %0;" : "+l"(d) : "l"(a), "l"(b))

__device__ __forceinline__ float fast_tanh(float x) {
    float z; asm("ex2.approx.f32 %0, %1;" : "=f"(z) : "f"(2.8853900817779268f * x));
    float r; asm("rcp.approx.f32 %0, %1;" : "=f"(r) : "f"(1.0f + z));
    return __fmaf_rn(-2.0f, r, 1.0f);
}
__device__ __forceinline__ float fast_sigmoid(float x) {
    float z; asm("ex2.approx.f32 %0, %1;" : "=f"(z) : "f"(-1.4426950408889634f * x));
    float r; asm("rcp.approx.f32 %0, %1;" : "=f"(r) : "f"(1.0f + z));
    return r;
}

// stage a 32x128 weight chunk into smem (512 threads, 8 floats each)
__device__ __forceinline__ void stageW(float* sW, const float* __restrict__ Wg,
                                       int kc, int tid) {
    int idx = tid * 8;
    const float4* g = (const float4*)(Wg + (kc + (idx >> 7)) * HID + (idx & 127));
    *(float4*)(sW + idx)     = g[0];
    *(float4*)(sW + idx + 4) = g[1];
}

// ---------------- 128xK x 128 register-tiled GEMM, 512 threads ----------------
// thread (ty,tx): rows ty*4..+3, cols {4tx..+3, 64+4tx..+3}
// INIT_HD: acc init = HD1[node][cols] + l2[row]*Wl2[cols]  (GEMM1)
// else:    acc init = bias[cols]
// NOTE: chunk-0 staging + barrier run FIRST so every smem region written by
// other threads before the call (HD1, src, gated rows) is ordered before any
// read in here.
template<bool INIT_HD>
__device__ __forceinline__ void gemm128(
    float* sm, const float* src, const float* __restrict__ Wg,
    const float* __restrict__ bias, float* dst, int K, int tid)
{
    const int tx = tid & 15, ty = tid >> 4;
    const int r0 = ty * 4;
    const int c0 = 4 * tx, c1 = 64 + 4 * tx;
    float* sW = sm + OFF_W;

    stageW(sW, Wg, 0, tid);
    __syncthreads();               // orders all pre-call smem writes too

    u64 acc[4][4];
    if (INIT_HD) {
        const float* hd1 = sm + OFF_HD1 + (ty >> 2) * MS;
        u64 h[4], wl[4];
        h[0] = *(const u64*)(hd1 + c0); h[1] = *(const u64*)(hd1 + c0 + 2);
        h[2] = *(const u64*)(hd1 + c1); h[3] = *(const u64*)(hd1 + c1 + 2);
        const float* wl2 = sm + OFF_WL2;
        wl[0] = *(const u64*)(wl2 + c0); wl[1] = *(const u64*)(wl2 + c0 + 2);
        wl[2] = *(const u64*)(wl2 + c1); wl[3] = *(const u64*)(wl2 + c1 + 2);
        #pragma unroll
        for (int i = 0; i < 4; i++) {
            float l2v = sm[OFF_L2 + r0 + i];
            u64 lp = pack2(l2v, l2v);
            #pragma unroll
            for (int p = 0; p < 4; p++) { acc[i][p] = h[p]; FMA2(acc[i][p], lp, wl[p]); }
        }
    } else {
        u64 bp[4];
        bp[0] = *(const u64*)(bias + c0); bp[1] = *(const u64*)(bias + c0 + 2);
        bp[2] = *(const u64*)(bias + c1); bp[3] = *(const u64*)(bias + c1 + 2);
        #pragma unroll
        for (int i = 0; i < 4; i++)
            #pragma unroll
            for (int p = 0; p < 4; p++) acc[i][p] = bp[p];
    }

    int buf = 0;
    for (int kc = 0; kc < K; kc += 32) {
        if (kc + 32 < K) stageW(sW + (buf ^ 1) * 4096, Wg, kc + 32, tid);
        const float* wb = sW + buf * 4096;
        #pragma unroll
        for (int k4 = 0; k4 < 8; k4++) {
            float4 xv[4];
            #pragma unroll
            for (int i = 0; i < 4; i++)
                xv[i] = *(const float4*)(src + (r0 + i) * MS + kc + k4 * 4);
            #pragma unroll
            for (int u = 0; u < 4; u++) {
                const float* wr = wb + (k4 * 4 + u) * HID;
                u64 w[4];
                w[0] = *(const u64*)(wr + c0); w[1] = *(const u64*)(wr + c0 + 2);
                w[2] = *(const u64*)(wr + c1); w[3] = *(const u64*)(wr + c1 + 2);
                #pragma unroll
                for (int i = 0; i < 4; i++) {
                    float xs = (u == 0) ? xv[i].x : (u == 1) ? xv[i].y
                             : (u == 2) ? xv[i].z : xv[i].w;
                    u64 xp = pack2(xs, xs);
                    FMA2(acc[i][0], xp, w[0]); FMA2(acc[i][1], xp, w[1]);
                    FMA2(acc[i][2], xp, w[2]); FMA2(acc[i][3], xp, w[3]);
                }
            }
        }
        __syncthreads();
        buf ^= 1;
    }

    #pragma unroll
    for (int i = 0; i < 4; i++) {
        float v[8];
        unpack2(acc[i][0], v[0], v[1]); unpack2(acc[i][1], v[2], v[3]);
        unpack2(acc[i][2], v[4], v[5]); unpack2(acc[i][3], v[6], v[7]);
        float4 o0, o1;
        o0.x = fast_tanh(v[0]); o0.y = fast_tanh(v[1]);
        o0.z = fast_tanh(v[2]); o0.w = fast_tanh(v[3]);
        o1.x = fast_tanh(v[4]); o1.y = fast_tanh(v[5]);
        o1.z = fast_tanh(v[6]); o1.w = fast_tanh(v[7]);
        *(float4*)(dst + (r0 + i) * MS + c0) = o0;
        *(float4*)(dst + (r0 + i) * MS + c1) = o1;
    }
}

// ---------------- fused EGNN layer ----------------
__global__ void __launch_bounds__(THREADS, 1)
egnn_kernel(const float* __restrict__ coords, const float* __restrict__ hidden,
            const void*  __restrict__ edges,
            const float* __restrict__ W1,  const float* __restrict__ b1,
            const float* __restrict__ W2,  const float* __restrict__ b2,
            const float* __restrict__ Wa,  const float* __restrict__ ba,
            const float* __restrict__ Wc1, const float* __restrict__ bc1,
            const float* __restrict__ Wc2,
            const float* __restrict__ Wh1, const float* __restrict__ bh1,
            const float* __restrict__ Wh2, const float* __restrict__ bh2,
            float* __restrict__ out, int N)
{
    extern __shared__ float sm[];
    int* smi   = (int*)(sm + OFF_INT);
    int* sSrc  = smi;
    int* sDst  = smi + 128;
    int* sDstN = smi + 256;

    const int tid   = threadIdx.x;
    const int E     = N * DEG;
    const int ebase = blockIdx.x * EPC;

    const int*       e32 = (const int*)edges;
    const long long* e64 = (const long long*)edges;
    const bool is64 = (e32[1] == 0) && (e32[3] == 0);

    // ---- phase 1: edge ids, dif/l2, small weight vectors ----
    if (tid < EPC) {
        int e = ebase + tid;
        int s, d;
        if (is64) { s = (int)e64[e]; d = (int)e64[E + e]; }
        else      { s = e32[e];      d = e32[E + e]; }
        sSrc[tid] = s; sDst[tid] = d;
        if ((tid & 15) == 0) sDstN[tid >> 4] = d;
        float dx = coords[s * 3 + 0] - coords[d * 3 + 0];
        float dy = coords[s * 3 + 1] - coords[d * 3 + 1];
        float dz = coords[s * 3 + 2] - coords[d * 3 + 2];
        sm[OFF_DIF + tid * 3 + 0] = dx;
        sm[OFF_DIF + tid * 3 + 1] = dy;
        sm[OFF_DIF + tid * 3 + 2] = dz;
        sm[OFF_L2 + tid] = sqrtf(dx * dx + dy * dy + dz * dz);
    } else if (tid < 256) {
        sm[OFF_WL2 + tid - 128] = W1[256 * HID + (tid - 128)];
    } else if (tid < 384) {
        sm[OFF_WA + tid - 256] = Wa[tid - 256];
    } else {
        sm[OFF_WC2 + tid - 384] = Wc2[tid - 384];
    }
    __syncthreads();

    // ---- phase 2: load h_src rows (128) and raw hidden[dst] (8) ----
    {
        int w = tid >> 5, lane = tid & 31;
        #pragma unroll
        for (int r = 0; r < 8; r++) {
            int e = w * 8 + r;
            *(float4*)(sm + OFF_XA + e * MS + 4 * lane) =
                *(const float4*)(hidden + (size_t)sSrc[e] * HID + 4 * lane);
        }
    }
    if (tid < 256) {
        int n = tid >> 5, lane = tid & 31;
        *(float4*)(sm + OFF_HD + n * MS + 4 * lane) =
            *(const float4*)(hidden + (size_t)sDstN[n] * HID + 4 * lane);
    }
    __syncthreads();

    // ---- hd1[n][j] = b1[j] + h_dst[n] @ W1[128:256]  (tiny, direct L2 reads) ----
    {
        int j = tid & 127, ng = tid >> 7;
        int n0 = ng * 2, n1 = n0 + 1;
        float a0 = b1[j], a1 = a0;
        #pragma unroll 8
        for (int k = 0; k < 128; k++) {
            float w = W1[(128 + k) * HID + j];
            a0 = __fmaf_rn(sm[OFF_HD + n0 * MS + k], w, a0);
            a1 = __fmaf_rn(sm[OFF_HD + n1 * MS + k], w, a1);
        }
        sm[OFF_HD1 + n0 * MS + j] = a0;
        sm[OFF_HD1 + n1 * MS + j] = a1;
    }
    // (gemm128's entry barrier orders hd1 before any thread reads it)

    // ---- m1 = tanh(h_src@W1[:128] + hd1 + l2*Wl2) ----
    gemm128<true>(sm, sm + OFF_XA, W1, nullptr, sm + OFF_B, 128, tid);
    // ---- m2 = tanh(m1 @ W2 + b2) -> A0 (reuses XA) ----
    gemm128<false>(sm, sm + OFF_B, W2, b2, sm + OFF_XA, 128, tid);
    __syncthreads();

    // ---- attention gate (quad per edge): m *= sigmoid(m.Wa + ba) ----
    {
        int e = tid >> 2, q = tid & 3;
        float4* row = (float4*)(sm + OFF_XA + e * MS + q * 32);
        const float4* wa = (const float4*)(sm + OFF_WA + q * 32);
        float s = 0.f;
        #pragma unroll
        for (int k = 0; k < 8; k++) {
            float4 r = row[k], w = wa[k];
            s = __fmaf_rn(r.x, w.x, s); s = __fmaf_rn(r.y, w.y, s);
            s = __fmaf_rn(r.z, w.z, s); s = __fmaf_rn(r.w, w.w, s);
        }
        s += __shfl_xor_sync(0xffffffffu, s, 1);
        s += __shfl_xor_sync(0xffffffffu, s, 2);
        float g = fast_sigmoid(s + ba[0]);
        #pragma unroll
        for (int k = 0; k < 8; k++) {
            float4 r = row[k];
            r.x *= g; r.y *= g; r.z *= g; r.w *= g;
            row[k] = r;
        }
    }
    // ---- mc = tanh(m @ Wc1 + bc1) -> B ----
    gemm128<false>(sm, sm + OFF_XA, Wc1, bc1, sm + OFF_B, 128, tid);
    __syncthreads();

    // ---- c = tanh(mc . Wc2) (quad per edge) ----
    {
        int e = tid >> 2, q = tid & 3;
        const float4* row = (const float4*)(sm + OFF_B + e * MS + q * 32);
        const float4* wc = (const float4*)(sm + OFF_WC2 + q * 32);
        float s = 0.f;
        #pragma unroll
        for (int k = 0; k < 8; k++) {
            float4 r = row[k], w = wc[k];
            s = __fmaf_rn(r.x, w.x, s); s = __fmaf_rn(r.y, w.y, s);
            s = __fmaf_rn(r.z, w.z, s); s = __fmaf_rn(r.w, w.w, s);
        }
        s += __shfl_xor_sync(0xffffffffu, s, 1);
        s += __shfl_xor_sync(0xffffffffu, s, 2);
        if (q == 0) sm[OFF_C + e] = fast_tanh(s);
    }
    // ---- m_i = segment-sum of gated m (A0) ----
    {
        int j = tid & 127, ng = tid >> 7;
        #pragma unroll
        for (int t = 0; t < 2; t++) {
            int n = ng * 2 + t;
            float s = 0.f;
            const float* base = sm + OFF_XA + (n * DEG) * MS + j;
            #pragma unroll
            for (int d = 0; d < DEG; d++) s += base[d * MS];
            sm[OFF_MI + n * MS + j] = s;
        }
    }
    __syncthreads();

    // ---- coords_out ----
    if (tid < NPC * 3) {
        int n = tid / 3, d = tid - n * 3;
        float s = 0.f;
        #pragma unroll
        for (int k = 0; k < DEG; k++)
            s = __fmaf_rn(sm[OFF_C + n * DEG + k],
                          sm[OFF_DIF + (n * DEG + k) * 3 + d], s);
        int node = sDstN[n];
        out[node * 3 + d] = coords[node * 3 + d] + s * (1.0f / DEG);
    }

    // ---- node MLP: th = tanh([h_dst | m_i] @ Wh1 + bh1) ----
    {
        int j = tid & 127, ng = tid >> 7;
        int n0 = ng * 2, n1 = n0 + 1;
        float a0 = bh1[j], a1 = a0;
        #pragma unroll 8
        for (int k = 0; k < 128; k++) {
            float w = Wh1[k * HID + j];
            a0 = __fmaf_rn(sm[OFF_HD + n0 * MS + k], w, a0);
            a1 = __fmaf_rn(sm[OFF_HD + n1 * MS + k], w, a1);
        }
        #pragma unroll 8
        for (int k = 0; k < 128; k++) {
            float w = Wh1[(128 + k) * HID + j];
            a0 = __fmaf_rn(sm[OFF_MI + n0 * MS + k], w, a0);
            a1 = __fmaf_rn(sm[OFF_MI + n1 * MS + k], w, a1);
        }
        sm[OFF_TH + n0 * MS + j] = fast_tanh(a0);
        sm[OFF_TH + n1 * MS + j] = fast_tanh(a1);
    }
    __syncthreads();

    // ---- hidden_out = hidden + th @ Wh2 + bh2 ----
    {
        int j = tid & 127, ng = tid >> 7;
        int n0 = ng * 2, n1 = n0 + 1;
        float a0 = bh2[j], a1 = a0;
        #pragma unroll 8
        for (int k = 0; k < 128; k++) {
            float w = Wh2[k * HID + j];
            a0 = __fmaf_rn(sm[OFF_TH + n0 * MS + k], w, a0);
            a1 = __fmaf_rn(sm[OFF_TH + n1 * MS + k], w, a1);
        }
        float* oh = out + (size_t)N * 3;
        oh[(size_t)sDstN[n0] * HID + j] = sm[OFF_HD + n0 * MS + j] + a0;
        oh[(size_t)sDstN[n1] * HID + j] = sm[OFF_HD + n1 * MS + j] + a1;
    }
}

// ---------------- launch ----------------
extern "C" void kernel_launch(void* const* d_in, const int* in_sizes, int n_in,
                              void* d_out, int out_size)
{
    const float* coords = (const float*)d_in[0];
    const float* hidden = (const float*)d_in[1];
    const void*  edges  = d_in[2];
    const float* W1  = (const float*)d_in[3];
    const float* b1  = (const float*)d_in[4];
    const float* W2  = (const float*)d_in[5];
    const float* b2  = (const float*)d_in[6];
    const float* Wa  = (const float*)d_in[7];
    const float* ba  = (const float*)d_in[8];
    const float* Wc1 = (const float*)d_in[9];
    const float* bc1 = (const float*)d_in[10];
    const float* Wc2 = (const float*)d_in[11];
    const float* Wh1 = (const float*)d_in[12];
    const float* bh1 = (const float*)d_in[13];
    const float* Wh2 = (const float*)d_in[14];
    const float* bh2 = (const float*)d_in[15];

    int N = in_sizes[0] / 3;
    float* out = (float*)d_out;

    cudaFuncSetAttribute(egnn_kernel, cudaFuncAttributeMaxDynamicSharedMemorySize,
                         SMEM_BYTES);
    egnn_kernel<<<N / NPC, THREADS, SMEM_BYTES>>>(
        coords, hidden, edges, W1, b1, W2, b2, Wa, ba, Wc1, bc1, Wc2,
        Wh1, bh1, Wh2, bh2, out, N);
}

// round 11
// speedup vs baseline: 1.1125x; 1.0049x over previous
#include <cuda_runtime.h>
#include <cstdint>

// ---------------- problem constants ----------------
#define NPC     4            // nodes per CTA  (2 CTAs co-resident per SM)
#define DEG     16
#define EPC     64           // edges per CTA
#define HID     128
#define THREADS 256

#define MS  132              // row stride for 128-col tiles (16B aligned)

// ---------------- smem layout (float offsets) ----------------
#define OFF_XA   0           // 64*132 = 8448   (h_src; later A0 = gated m)
#define OFF_B    8448        // 64*132          (m1; later mc)
#define OFF_W    16896       // 2 * 32*128 = 8192 (double-buffered weight chunks)
#define OFF_HD   25088       // 4*132  raw hidden[dst]
#define OFF_HD1  25616       // 4*132  h_dst @ W1[128:256] + b1
#define OFF_MI   26144       // 4*132  m_i
#define OFF_TH   26672       // 4*132  node-MLP hidden
#define OFF_DIF  27200       // 64*3
#define OFF_L2   27392       // 64
#define OFF_C    27456       // 64
#define OFF_WL2  27520       // 128 (W1 row 256)
#define OFF_WA   27648       // 128
#define OFF_WC2  27776       // 128
#define OFF_INT  27904       // ints: src[64], dst[64], dstN[4]
#define SMEM_FLOATS 28040
#define SMEM_BYTES  (SMEM_FLOATS * 4)   // 112160 B; x2 CTAs = 224 KB/SM

typedef unsigned long long u64;

// ---------------- helpers ----------------
__device__ __forceinline__ u64 pack2(float lo, float hi) {
    u64 r; asm("mov.b64 %0, {%1, %2};" : "=l"(r) : "f"(lo), "f"(hi)); return r;
}
__device__ __forceinline__ void unpack2(u64 v, float& lo, float& hi) {
    asm("mov.b64 {%0, %1}, %2;" : "=f"(lo), "=f"(hi) : "l"(v));
}
#define FMA2(d, a, b) asm("fma.rn.f32x2 %0, %1, %2, %0;" : "+l"(d) : "l"(a), "l"(b))

__device__ __forceinline__ float fast_tanh(float x) {
    float z; asm("ex2.approx.f32 %0, %1;" : "=f"(z) : "f"(2.8853900817779268f * x));
    float r; asm("rcp.approx.f32 %0, %1;" : "=f"(r) : "f"(1.0f + z));
    return __fmaf_rn(-2.0f, r, 1.0f);
}
__device__ __forceinline__ float fast_sigmoid(float x) {
    float z; asm("ex2.approx.f32 %0, %1;" : "=f"(z) : "f"(-1.4426950408889634f * x));
    float r; asm("rcp.approx.f32 %0, %1;" : "=f"(r) : "f"(1.0f + z));
    return r;
}

// stage a 32x128 weight chunk into smem (256 threads, 16 floats each)
__device__ __forceinline__ void stageW(float* sW, const float* __restrict__ Wg,
                                       int kc, int tid) {
    int idx = tid * 16;    // 16 consecutive floats, never crossing a 128-col row
    const float4* g = (const float4*)(Wg + (kc + (idx >> 7)) * HID + (idx & 127));
    *(float4*)(sW + idx)      = g[0];
    *(float4*)(sW + idx + 4)  = g[1];
    *(float4*)(sW + idx + 8)  = g[2];
    *(float4*)(sW + idx + 12) = g[3];
}

// ---------------- 64xK x 128 register-tiled GEMM, 256 threads ----------------
// thread (ty,tx), tx=tid&15, ty=tid>>4: rows ty*4..+3 (64), cols {4tx..+3, 64+4tx..+3}
// INIT_HD: acc init = HD1[node][cols] + l2[row]*Wl2[cols]  (GEMM1)
// else:    acc init = bias[cols]
// Chunk-0 staging + barrier run FIRST so every smem region written by other
// threads before the call (HD1, src, gated rows) is ordered before any read.
template<bool INIT_HD>
__device__ __forceinline__ void gemm64(
    float* sm, const float* src, const float* __restrict__ Wg,
    const float* __restrict__ bias, float* dst, int K, int tid)
{
    const int tx = tid & 15, ty = tid >> 4;
    const int r0 = ty * 4;
    const int c0 = 4 * tx, c1 = 64 + 4 * tx;
    float* sW = sm + OFF_W;

    stageW(sW, Wg, 0, tid);
    __syncthreads();               // orders all pre-call smem writes too

    u64 acc[4][4];
    if (INIT_HD) {
        const float* hd1 = sm + OFF_HD1 + (ty >> 2) * MS;   // node = row/16 = ty/4
        u64 h[4], wl[4];
        h[0] = *(const u64*)(hd1 + c0); h[1] = *(const u64*)(hd1 + c0 + 2);
        h[2] = *(const u64*)(hd1 + c1); h[3] = *(const u64*)(hd1 + c1 + 2);
        const float* wl2 = sm + OFF_WL2;
        wl[0] = *(const u64*)(wl2 + c0); wl[1] = *(const u64*)(wl2 + c0 + 2);
        wl[2] = *(const u64*)(wl2 + c1); wl[3] = *(const u64*)(wl2 + c1 + 2);
        #pragma unroll
        for (int i = 0; i < 4; i++) {
            float l2v = sm[OFF_L2 + r0 + i];
            u64 lp = pack2(l2v, l2v);
            #pragma unroll
            for (int p = 0; p < 4; p++) { acc[i][p] = h[p]; FMA2(acc[i][p], lp, wl[p]); }
        }
    } else {
        u64 bp[4];
        bp[0] = *(const u64*)(bias + c0); bp[1] = *(const u64*)(bias + c0 + 2);
        bp[2] = *(const u64*)(bias + c1); bp[3] = *(const u64*)(bias + c1 + 2);
        #pragma unroll
        for (int i = 0; i < 4; i++)
            #pragma unroll
            for (int p = 0; p < 4; p++) acc[i][p] = bp[p];
    }

    int buf = 0;
    for (int kc = 0; kc < K; kc += 32) {
        if (kc + 32 < K) stageW(sW + (buf ^ 1) * 4096, Wg, kc + 32, tid);
        const float* wb = sW + buf * 4096;
        #pragma unroll
        for (int k4 = 0; k4 < 8; k4++) {
            float4 xv[4];
            #pragma unroll
            for (int i = 0; i < 4; i++)
                xv[i] = *(const float4*)(src + (r0 + i) * MS + kc + k4 * 4);
            #pragma unroll
            for (int u = 0; u < 4; u++) {
                const float* wr = wb + (k4 * 4 + u) * HID;
                u64 w[4];
                w[0] = *(const u64*)(wr + c0); w[1] = *(const u64*)(wr + c0 + 2);
                w[2] = *(const u64*)(wr + c1); w[3] = *(const u64*)(wr + c1 + 2);
                #pragma unroll
                for (int i = 0; i < 4; i++) {
                    float xs = (u == 0) ? xv[i].x : (u == 1) ? xv[i].y
                             : (u == 2) ? xv[i].z : xv[i].w;
                    u64 xp = pack2(xs, xs);
                    FMA2(acc[i][0], xp, w[0]); FMA2(acc[i][1], xp, w[1]);
                    FMA2(acc[i][2], xp, w[2]); FMA2(acc[i][3], xp, w[3]);
                }
            }
        }
        __syncthreads();
        buf ^= 1;
    }

    #pragma unroll
    for (int i = 0; i < 4; i++) {
        float v[8];
        unpack2(acc[i][0], v[0], v[1]); unpack2(acc[i][1], v[2], v[3]);
        unpack2(acc[i][2], v[4], v[5]); unpack2(acc[i][3], v[6], v[7]);
        float4 o0, o1;
        o0.x = fast_tanh(v[0]); o0.y = fast_tanh(v[1]);
        o0.z = fast_tanh(v[2]); o0.w = fast_tanh(v[3]);
        o1.x = fast_tanh(v[4]); o1.y = fast_tanh(v[5]);
        o1.z = fast_tanh(v[6]); o1.w = fast_tanh(v[7]);
        *(float4*)(dst + (r0 + i) * MS + c0) = o0;
        *(float4*)(dst + (r0 + i) * MS + c1) = o1;
    }
}

// ---------------- fused EGNN layer ----------------
__global__ void __launch_bounds__(THREADS, 2)
egnn_kernel(const float* __restrict__ coords, const float* __restrict__ hidden,
            const void*  __restrict__ edges,
            const float* __restrict__ W1,  const float* __restrict__ b1,
            const float* __restrict__ W2,  const float* __restrict__ b2,
            const float* __restrict__ Wa,  const float* __restrict__ ba,
            const float* __restrict__ Wc1, const float* __restrict__ bc1,
            const float* __restrict__ Wc2,
            const float* __restrict__ Wh1, const float* __restrict__ bh1,
            const float* __restrict__ Wh2, const float* __restrict__ bh2,
            float* __restrict__ out, int N)
{
    extern __shared__ float sm[];
    int* smi   = (int*)(sm + OFF_INT);
    int* sSrc  = smi;
    int* sDst  = smi + EPC;
    int* sDstN = smi + 2 * EPC;

    const int tid   = threadIdx.x;
    const int E     = N * DEG;
    const int ebase = blockIdx.x * EPC;

    const int*       e32 = (const int*)edges;
    const long long* e64 = (const long long*)edges;
    const bool is64 = (e32[1] == 0) && (e32[3] == 0);

    // ---- phase 1: edge ids, dif/l2, small weight vectors ----
    if (tid < EPC) {
        int e = ebase + tid;
        int s, d;
        if (is64) { s = (int)e64[e]; d = (int)e64[E + e]; }
        else      { s = e32[e];      d = e32[E + e]; }
        sSrc[tid] = s; sDst[tid] = d;
        if ((tid & 15) == 0) sDstN[tid >> 4] = d;
        float dx = coords[s * 3 + 0] - coords[d * 3 + 0];
        float dy = coords[s * 3 + 1] - coords[d * 3 + 1];
        float dz = coords[s * 3 + 2] - coords[d * 3 + 2];
        sm[OFF_DIF + tid * 3 + 0] = dx;
        sm[OFF_DIF + tid * 3 + 1] = dy;
        sm[OFF_DIF + tid * 3 + 2] = dz;
        sm[OFF_L2 + tid] = sqrtf(dx * dx + dy * dy + dz * dz);
    } else if (tid < 192) {
        sm[OFF_WL2 + tid - 64] = W1[256 * HID + (tid - 64)];
    }
    if (tid < 128) sm[OFF_WA + tid] = Wa[tid];
    else           sm[OFF_WC2 + tid - 128] = Wc2[tid - 128];
    __syncthreads();

    // ---- phase 2: load h_src rows (64) and raw hidden[dst] (4) ----
    {
        int w = tid >> 5, lane = tid & 31;   // 8 warps x 8 rows
        #pragma unroll
        for (int r = 0; r < 8; r++) {
            int e = w * 8 + r;
            *(float4*)(sm + OFF_XA + e * MS + 4 * lane) =
                *(const float4*)(hidden + (size_t)sSrc[e] * HID + 4 * lane);
        }
    }
    if (tid < 128) {
        int n = tid >> 5, lane = tid & 31;
        *(float4*)(sm + OFF_HD + n * MS + 4 * lane) =
            *(const float4*)(hidden + (size_t)sDstN[n] * HID + 4 * lane);
    }
    __syncthreads();

    // ---- hd1[n][j] = b1[j] + h_dst[n] @ W1[128:256]  (tiny, direct L2 reads) ----
    {
        int j = tid & 127, ng = tid >> 7;    // ng in {0,1} -> 2 nodes each
        int n0 = ng * 2, n1 = n0 + 1;
        float a0 = b1[j], a1 = a0;
        #pragma unroll 8
        for (int k = 0; k < 128; k++) {
            float w = W1[(128 + k) * HID + j];
            a0 = __fmaf_rn(sm[OFF_HD + n0 * MS + k], w, a0);
            a1 = __fmaf_rn(sm[OFF_HD + n1 * MS + k], w, a1);
        }
        sm[OFF_HD1 + n0 * MS + j] = a0;
        sm[OFF_HD1 + n1 * MS + j] = a1;
    }
    // (gemm64's entry barrier orders hd1 before any thread reads it)

    // ---- m1 = tanh(h_src@W1[:128] + hd1 + l2*Wl2) ----
    gemm64<true>(sm, sm + OFF_XA, W1, nullptr, sm + OFF_B, 128, tid);
    // ---- m2 = tanh(m1 @ W2 + b2) -> XA ----
    gemm64<false>(sm, sm + OFF_B, W2, b2, sm + OFF_XA, 128, tid);
    __syncthreads();

    // ---- attention gate (quad per edge): m *= sigmoid(m.Wa + ba) ----
    {
        int e = tid >> 2, q = tid & 3;       // 64 edges x 4 threads
        float4* row = (float4*)(sm + OFF_XA + e * MS + q * 32);
        const float4* wa = (const float4*)(sm + OFF_WA + q * 32);
        float s = 0.f;
        #pragma unroll
        for (int k = 0; k < 8; k++) {
            float4 r = row[k], w = wa[k];
            s = __fmaf_rn(r.x, w.x, s); s = __fmaf_rn(r.y, w.y, s);
            s = __fmaf_rn(r.z, w.z, s); s = __fmaf_rn(r.w, w.w, s);
        }
        s += __shfl_xor_sync(0xffffffffu, s, 1);
        s += __shfl_xor_sync(0xffffffffu, s, 2);
        float g = fast_sigmoid(s + ba[0]);
        #pragma unroll
        for (int k = 0; k < 8; k++) {
            float4 r = row[k];
            r.x *= g; r.y *= g; r.z *= g; r.w *= g;
            row[k] = r;
        }
    }
    // ---- mc = tanh(m @ Wc1 + bc1) -> B ----
    gemm64<false>(sm, sm + OFF_XA, Wc1, bc1, sm + OFF_B, 128, tid);
    __syncthreads();

    // ---- c = tanh(mc . Wc2) (quad per edge) ----
    {
        int e = tid >> 2, q = tid & 3;
        const float4* row = (const float4*)(sm + OFF_B + e * MS + q * 32);
        const float4* wc = (const float4*)(sm + OFF_WC2 + q * 32);
        float s = 0.f;
        #pragma unroll
        for (int k = 0; k < 8; k++) {
            float4 r = row[k], w = wc[k];
            s = __fmaf_rn(r.x, w.x, s); s = __fmaf_rn(r.y, w.y, s);
            s = __fmaf_rn(r.z, w.z, s); s = __fmaf_rn(r.w, w.w, s);
        }
        s += __shfl_xor_sync(0xffffffffu, s, 1);
        s += __shfl_xor_sync(0xffffffffu, s, 2);
        if (q == 0) sm[OFF_C + e] = fast_tanh(s);
    }
    // ---- m_i = segment-sum of gated m (XA) ----
    {
        int j = tid & 127, ng = tid >> 7;
        #pragma unroll
        for (int t = 0; t < 2; t++) {
            int n = ng * 2 + t;              // 4 nodes
            float s = 0.f;
            const float* base = sm + OFF_XA + (n * DEG) * MS + j;
            #pragma unroll
            for (int d = 0; d < DEG; d++) s += base[d * MS];
            sm[OFF_MI + n * MS + j] = s;
        }
    }
    __syncthreads();

    // ---- coords_out ----
    if (tid < NPC * 3) {
        int n = tid / 3, d = tid - n * 3;
        float s = 0.f;
        #pragma unroll
        for (int k = 0; k < DEG; k++)
            s = __fmaf_rn(sm[OFF_C + n * DEG + k],
                          sm[OFF_DIF + (n * DEG + k) * 3 + d], s);
        int node = sDstN[n];
        out[node * 3 + d] = coords[node * 3 + d] + s * (1.0f / DEG);
    }

    // ---- node MLP: th = tanh([h_dst | m_i] @ Wh1 + bh1) ----
    {
        int j = tid & 127, ng = tid >> 7;
        int n0 = ng * 2, n1 = n0 + 1;
        float a0 = bh1[j], a1 = a0;
        #pragma unroll 8
        for (int k = 0; k < 128; k++) {
            float w = Wh1[k * HID + j];
            a0 = __fmaf_rn(sm[OFF_HD + n0 * MS + k], w, a0);
            a1 = __fmaf_rn(sm[OFF_HD + n1 * MS + k], w, a1);
        }
        #pragma unroll 8
        for (int k = 0; k < 128; k++) {
            float w = Wh1[(128 + k) * HID + j];
            a0 = __fmaf_rn(sm[OFF_MI + n0 * MS + k], w, a0);
            a1 = __fmaf_rn(sm[OFF_MI + n1 * MS + k], w, a1);
        }
        sm[OFF_TH + n0 * MS + j] = fast_tanh(a0);
        sm[OFF_TH + n1 * MS + j] = fast_tanh(a1);
    }
    __syncthreads();

    // ---- hidden_out = hidden + th @ Wh2 + bh2 ----
    {
        int j = tid & 127, ng = tid >> 7;
        int n0 = ng * 2, n1 = n0 + 1;
        float a0 = bh2[j], a1 = a0;
        #pragma unroll 8
        for (int k = 0; k < 128; k++) {
            float w = Wh2[k * HID + j];
            a0 = __fmaf_rn(sm[OFF_TH + n0 * MS + k], w, a0);
            a1 = __fmaf_rn(sm[OFF_TH + n1 * MS + k], w, a1);
        }
        float* oh = out + (size_t)N * 3;
        oh[(size_t)sDstN[n0] * HID + j] = sm[OFF_HD + n0 * MS + j] + a0;
        oh[(size_t)sDstN[n1] * HID + j] = sm[OFF_HD + n1 * MS + j] + a1;
    }
}

// ---------------- launch ----------------
extern "C" void kernel_launch(void* const* d_in, const int* in_sizes, int n_in,
                              void* d_out, int out_size)
{
    const float* coords = (const float*)d_in[0];
    const float* hidden = (const float*)d_in[1];
    const void*  edges  = d_in[2];
    const float* W1  = (const float*)d_in[3];
    const float* b1  = (const float*)d_in[4];
    const float* W2  = (const float*)d_in[5];
    const float* b2  = (const float*)d_in[6];
    const float* Wa  = (const float*)d_in[7];
    const float* ba  = (const float*)d_in[8];
    const float* Wc1 = (const float*)d_in[9];
    const float* bc1 = (const float*)d_in[10];
    const float* Wc2 = (const float*)d_in[11];
    const float* Wh1 = (const float*)d_in[12];
    const float* bh1 = (const float*)d_in[13];
    const float* Wh2 = (const float*)d_in[14];
    const float* bh2 = (const float*)d_in[15];

    int N = in_sizes[0] / 3;
    float* out = (float*)d_out;

    cudaFuncSetAttribute(egnn_kernel, cudaFuncAttributeMaxDynamicSharedMemorySize,
                         SMEM_BYTES);
    egnn_kernel<<<N / NPC, THREADS, SMEM_BYTES>>>(
        coords, hidden, edges, W1, b1, W2, b2, Wa, ba, Wc1, bc1, Wc2,
        Wh1, bh1, Wh2, bh2, out, N);
}

// round 15
// speedup vs baseline: 1.2965x; 1.1654x over previous
#include <cuda_runtime.h>
#include <cuda_bf16.h>
#include <mma.h>
#include <cstdint>

using namespace nvcuda;

// ---------------- problem constants ----------------
#define NPC     8
#define DEG     16
#define EPC     128
#define HID     128
#define THREADS 256
#define LDA     136          // bf16 elems per row (A operand buffers)
#define LDD     132          // fp32 elems per row (D scratch)

// ---------------- smem byte offsets ----------------
#define SM_AHI  0            // 128*136*2 = 34816
#define SM_ALO  34816
#define SM_D    69632        // fp32 128*132*4 = 67584
#define SM_HD   137216       // fp32 8*132*4 = 4224
#define SM_HD1  141440
#define SM_MI   145664
#define SM_TH   149888
#define SM_DIF  154112       // 128*3 fp32 = 1536
#define SM_L2E  155648       // 128 fp32
#define SM_C    156160
#define SM_WL2  156672       // W1 row 256
#define SM_WA   157184
#define SM_WC2  157696
#define SM_B2   158208
#define SM_BC1  158720
#define SM_INT  159232       // src[128] dst[128] dstN[8] = 1056 B
#define SMEM_BYTES 160320

// pre-split weights, ORIGINAL [k][n] layout (no transpose): 0=W1[:128], 1=W2, 2=Wc1
__device__ __align__(16) __nv_bfloat16 g_Whi[3][16384];
__device__ __align__(16) __nv_bfloat16 g_Wlo[3][16384];

__device__ __forceinline__ float fast_tanh(float x) {
    float z; asm("ex2.approx.f32 %0, %1;" : "=f"(z) : "f"(2.8853900817779268f * x));
    float r; asm("rcp.approx.f32 %0, %1;" : "=f"(r) : "f"(1.0f + z));
    return __fmaf_rn(-2.0f, r, 1.0f);
}
__device__ __forceinline__ float fast_sigmoid(float x) {
    float z; asm("ex2.approx.f32 %0, %1;" : "=f"(z) : "f"(-1.4426950408889634f * x));
    float r; asm("rcp.approx.f32 %0, %1;" : "=f"(r) : "f"(1.0f + z));
    return r;
}
__device__ __forceinline__ uint32_t pk2(float a, float b) {
    __nv_bfloat16 ha = __float2bfloat16(a), hb = __float2bfloat16(b);
    uint16_t ra = *reinterpret_cast<uint16_t*>(&ha), rb = *reinterpret_cast<uint16_t*>(&hb);
    return (uint32_t)ra | ((uint32_t)rb << 16);
}
// split x into bf16 hi + bf16 lo (lo = bf16(x - float(hi)))
__device__ __forceinline__ void split2(float a, float b, uint32_t& hi, uint32_t& lo) {
    __nv_bfloat16 ha = __float2bfloat16(a), hb = __float2bfloat16(b);
    float la = a - __bfloat162float(ha), lb = b - __bfloat162float(hb);
    uint16_t ra = *reinterpret_cast<uint16_t*>(&ha), rb = *reinterpret_cast<uint16_t*>(&hb);
    hi = (uint32_t)ra | ((uint32_t)rb << 16);
    lo = pk2(la, lb);
}

// ---------------- prep: split W1(src half), W2, Wc1 into bf16 hi/lo ----------------
__global__ void prep_kernel(const float* __restrict__ W1, const float* __restrict__ W2,
                            const float* __restrict__ Wc1) {
    int idx = blockIdx.x * 256 + threadIdx.x;      // 0..49151
    int which = idx >> 14, rem = idx & 16383;
    const float* W = (which == 0) ? W1 : (which == 1) ? W2 : Wc1;
    float v = W[rem];
    __nv_bfloat16 h = __float2bfloat16(v);
    g_Whi[which][rem] = h;
    g_Wlo[which][rem] = __float2bfloat16(v - __bfloat162float(h));
}

// ---------------- 128x128x128 hi/lo WMMA GEMM: D(smem fp32) = A(smem bf16) @ W(global) ----
// warp tile 32x64: warp_m = wid&3 (rows), warp_n = wid>>2 (cols)
__device__ __forceinline__ void gemm_wmma(char* smem,
                                          const __nv_bfloat16* __restrict__ Whi,
                                          const __nv_bfloat16* __restrict__ Wlo,
                                          int wid) {
    const int wm = (wid & 3) * 32, wn = (wid >> 2) * 64;
    const __nv_bfloat16* Ahi = (const __nv_bfloat16*)(smem + SM_AHI);
    const __nv_bfloat16* Alo = (const __nv_bfloat16*)(smem + SM_ALO);

    wmma::fragment<wmma::accumulator, 16, 16, 16, float> c[2][4];
    #pragma unroll
    for (int m = 0; m < 2; m++)
        #pragma unroll
        for (int n = 0; n < 4; n++) wmma::fill_fragment(c[m][n], 0.0f);

    #pragma unroll
    for (int k = 0; k < 8; k++) {
        wmma::fragment<wmma::matrix_b, 16, 16, 16, __nv_bfloat16, wmma::row_major> bh[4], bl[4];
        #pragma unroll
        for (int n = 0; n < 4; n++) {
            wmma::load_matrix_sync(bh[n], Whi + (k*16)*HID + wn + n*16, HID);
            wmma::load_matrix_sync(bl[n], Wlo + (k*16)*HID + wn + n*16, HID);
        }
        #pragma unroll
        for (int m = 0; m < 2; m++) {
            wmma::fragment<wmma::matrix_a, 16, 16, 16, __nv_bfloat16, wmma::row_major> ah, al;
            wmma::load_matrix_sync(ah, Ahi + (wm + m*16)*LDA + k*16, LDA);
            wmma::load_matrix_sync(al, Alo + (wm + m*16)*LDA + k*16, LDA);
            #pragma unroll
            for (int n = 0; n < 4; n++) {
                wmma::mma_sync(c[m][n], ah, bh[n], c[m][n]);
                wmma::mma_sync(c[m][n], ah, bl[n], c[m][n]);
                wmma::mma_sync(c[m][n], al, bh[n], c[m][n]);
            }
        }
    }
    float* D = (float*)(smem + SM_D);
    #pragma unroll
    for (int m = 0; m < 2; m++)
        #pragma unroll
        for (int n = 0; n < 4; n++)
            wmma::store_matrix_sync(D + (wm + m*16)*LDD + wn + n*16, c[m][n], LDD,
                                    wmma::mem_row_major);
}

// ---------------- main fused kernel ----------------
__global__ void __launch_bounds__(THREADS, 1)
egnn_mma_kernel(const float* __restrict__ coords, const float* __restrict__ hidden,
                const void* __restrict__ edges,
                const float* __restrict__ W1, const float* __restrict__ b1,
                const float* __restrict__ b2,
                const float* __restrict__ Wa, const float* __restrict__ ba,
                const float* __restrict__ bc1, const float* __restrict__ Wc2,
                const float* __restrict__ Wh1, const float* __restrict__ bh1,
                const float* __restrict__ Wh2, const float* __restrict__ bh2,
                float* __restrict__ out, int N)
{
    extern __shared__ char smem[];
    float* smf = (float*)smem;
    const int tid = threadIdx.x, wid = tid >> 5, lane = tid & 31;
    int* sSrc  = (int*)(smem + SM_INT);
    int* sDst  = sSrc + 128;
    int* sDstN = sSrc + 256;

    // ---- phase 1: edges, dif/l2, small vectors ----
    const int E = N * DEG, ebase = blockIdx.x * EPC;
    const int* e32 = (const int*)edges;
    const long long* e64 = (const long long*)edges;
    const bool is64 = (e32[1] == 0) && (e32[3] == 0);

    if (tid < EPC) {
        int e = ebase + tid, s, d;
        if (is64) { s = (int)e64[e]; d = (int)e64[E + e]; }
        else      { s = e32[e];      d = e32[E + e]; }
        sSrc[tid] = s; sDst[tid] = d;
        if ((tid & 15) == 0) sDstN[tid >> 4] = d;
        float dx = coords[s*3+0]-coords[d*3+0], dy = coords[s*3+1]-coords[d*3+1],
              dz = coords[s*3+2]-coords[d*3+2];
        smf[SM_DIF/4 + tid*3+0] = dx; smf[SM_DIF/4 + tid*3+1] = dy;
        smf[SM_DIF/4 + tid*3+2] = dz;
        smf[SM_L2E/4 + tid] = sqrtf(dx*dx+dy*dy+dz*dz);
        smf[SM_WA/4  + tid] = Wa[tid];
        smf[SM_WC2/4 + tid] = Wc2[tid];
    } else {
        int j = tid - 128;
        smf[SM_WL2/4 + j] = W1[256*HID + j];
        smf[SM_B2/4  + j] = b2[j];
        smf[SM_BC1/4 + j] = bc1[j];
    }
    __syncthreads();
    {   // HD: 8 nodes x 128 cols
        int n = tid >> 5;
        *(float4*)(smf + SM_HD/4 + n*LDD + 4*lane) =
            *(const float4*)(hidden + (size_t)sDstN[n]*HID + 4*lane);
    }
    __syncthreads();

    // ---- hd1 = b1 + h_dst @ W1[128:256]  (fp32 exact) ----
    {
        int j = tid & 127, ng = tid >> 7;
        float acc[4];
        #pragma unroll
        for (int t = 0; t < 4; t++) acc[t] = b1[j];
        for (int k = 0; k < 128; k++) {
            float w = W1[(128 + k)*HID + j];
            #pragma unroll
            for (int t = 0; t < 4; t++)
                acc[t] = __fmaf_rn(smf[SM_HD/4 + (ng*4+t)*LDD + k], w, acc[t]);
        }
        #pragma unroll
        for (int t = 0; t < 4; t++) smf[SM_HD1/4 + (ng*4+t)*LDD + j] = acc[t];
    }

    // ---- stage A = h_src (bf16 hi/lo, row-major) ----
    #pragma unroll
    for (int i = 0; i < 16; i++) {
        int e = i*8 + wid, k = lane * 4;
        float4 v = *(const float4*)(hidden + (size_t)sSrc[e]*HID + k);
        uint32_t h0, l0, h1, l1;
        split2(v.x, v.y, h0, l0); split2(v.z, v.w, h1, l1);
        *(uint2*)(smem + SM_AHI + (e*LDA + k)*2) = make_uint2(h0, h1);
        *(uint2*)(smem + SM_ALO + (e*LDA + k)*2) = make_uint2(l0, l1);
    }
    __syncthreads();

    // ================= GEMM 1: h_src @ W1[:128] =================
    gemm_wmma(smem, g_Whi[0], g_Wlo[0], wid);
    __syncthreads();

    // epi1: m1 = tanh(D + hd1 + l2*Wl2) -> A hi/lo
    {
        int r = tid >> 1, half = tid & 1, c0 = half * 64;
        const float* Drow = smf + SM_D/4 + r*LDD;
        const float* hd1  = smf + SM_HD1/4 + (r >> 4)*LDD;
        const float* wl2  = smf + SM_WL2/4;
        float l2v = smf[SM_L2E/4 + r];
        #pragma unroll 8
        for (int c = c0; c < c0 + 64; c += 4) {
            float t0 = fast_tanh(Drow[c]   + hd1[c]   + l2v*wl2[c]);
            float t1 = fast_tanh(Drow[c+1] + hd1[c+1] + l2v*wl2[c+1]);
            float t2 = fast_tanh(Drow[c+2] + hd1[c+2] + l2v*wl2[c+2]);
            float t3 = fast_tanh(Drow[c+3] + hd1[c+3] + l2v*wl2[c+3]);
            uint32_t h0, l0, h1, l1;
            split2(t0, t1, h0, l0); split2(t2, t3, h1, l1);
            *(uint2*)(smem + SM_AHI + (r*LDA + c)*2) = make_uint2(h0, h1);
            *(uint2*)(smem + SM_ALO + (r*LDA + c)*2) = make_uint2(l0, l1);
        }
    }
    __syncthreads();

    // ================= GEMM 2: m1 @ W2 =================
    gemm_wmma(smem, g_Whi[1], g_Wlo[1], wid);
    __syncthreads();

    // epi2 + gate: m2 = tanh(D + b2); g = sigmoid(m2.Wa + ba); m2 *= g  (pair per row)
    {
        int r = tid >> 1, half = tid & 1, c0 = half * 64;
        float* Drow = smf + SM_D/4 + r*LDD;
        const float* b2s = smf + SM_B2/4;
        const float* wa  = smf + SM_WA/4;
        float s = 0.f;
        #pragma unroll 16
        for (int c = c0; c < c0 + 64; c++) {
            float t = fast_tanh(Drow[c] + b2s[c]);
            Drow[c] = t;
            s = __fmaf_rn(t, wa[c], s);
        }
        s += __shfl_xor_sync(0xffffffffu, s, 1);
        float g = fast_sigmoid(s + ba[0]);
        #pragma unroll 16
        for (int c = c0; c < c0 + 64; c++) Drow[c] *= g;
    }
    __syncthreads();

    // m_i segment-sum (from D) + split gated m -> A hi/lo
    {
        int j = tid & 127, ng = tid >> 7;
        #pragma unroll
        for (int t = 0; t < 4; t++) {
            int n = ng*4 + t;
            float s = 0.f;
            const float* base = smf + SM_D/4 + (n*DEG)*LDD + j;
            #pragma unroll
            for (int d = 0; d < DEG; d++) s += base[d*LDD];
            smf[SM_MI/4 + n*LDD + j] = s;
        }
    }
    #pragma unroll
    for (int i = 0; i < 16; i++) {
        int e = i*8 + wid, k = lane * 4;
        float4 v = *(const float4*)(smf + SM_D/4 + e*LDD + k);
        uint32_t h0, l0, h1, l1;
        split2(v.x, v.y, h0, l0); split2(v.z, v.w, h1, l1);
        *(uint2*)(smem + SM_AHI + (e*LDA + k)*2) = make_uint2(h0, h1);
        *(uint2*)(smem + SM_ALO + (e*LDA + k)*2) = make_uint2(l0, l1);
    }
    __syncthreads();

    // ================= GEMM 3: m @ Wc1 =================
    gemm_wmma(smem, g_Whi[2], g_Wlo[2], wid);
    __syncthreads();

    // epi3: c = tanh( tanh(D + bc1) . Wc2 )
    {
        int r = tid >> 1, half = tid & 1, c0 = half * 64;
        const float* Drow = smf + SM_D/4 + r*LDD;
        const float* bc1s = smf + SM_BC1/4;
        const float* wc2  = smf + SM_WC2/4;
        float s = 0.f;
        #pragma unroll 16
        for (int c = c0; c < c0 + 64; c++)
            s = __fmaf_rn(fast_tanh(Drow[c] + bc1s[c]), wc2[c], s);
        s += __shfl_xor_sync(0xffffffffu, s, 1);
        if (half == 0) smf[SM_C/4 + r] = fast_tanh(s);
    }
    __syncthreads();

    // ---- coords_out ----
    if (tid < NPC*3) {
        int n = tid / 3, d = tid - n*3;
        float s = 0.f;
        #pragma unroll
        for (int k = 0; k < DEG; k++)
            s = __fmaf_rn(smf[SM_C/4 + n*DEG + k],
                          smf[SM_DIF/4 + (n*DEG + k)*3 + d], s);
        int node = sDstN[n];
        out[node*3 + d] = coords[node*3 + d] + s * (1.0f / DEG);
    }

    // ---- node MLP (fp32 exact) ----
    {
        int j = tid & 127, ng = tid >> 7;
        float acc[4];
        #pragma unroll
        for (int t = 0; t < 4; t++) acc[t] = bh1[j];
        for (int k = 0; k < 128; k++) {
            float w = Wh1[k*HID + j];
            #pragma unroll
            for (int t = 0; t < 4; t++)
                acc[t] = __fmaf_rn(smf[SM_HD/4 + (ng*4+t)*LDD + k], w, acc[t]);
        }
        for (int k = 0; k < 128; k++) {
            float w = Wh1[(128+k)*HID + j];
            #pragma unroll
            for (int t = 0; t < 4; t++)
                acc[t] = __fmaf_rn(smf[SM_MI/4 + (ng*4+t)*LDD + k], w, acc[t]);
        }
        #pragma unroll
        for (int t = 0; t < 4; t++) smf[SM_TH/4 + (ng*4+t)*LDD + j] = fast_tanh(acc[t]);
    }
    __syncthreads();
    {
        int j = tid & 127, ng = tid >> 7;
        float acc[4];
        #pragma unroll
        for (int t = 0; t < 4; t++) acc[t] = bh2[j];
        for (int k = 0; k < 128; k++) {
            float w = Wh2[k*HID + j];
            #pragma unroll
            for (int t = 0; t < 4; t++)
                acc[t] = __fmaf_rn(smf[SM_TH/4 + (ng*4+t)*LDD + k], w, acc[t]);
        }
        float* oh = out + (size_t)N*3;
        #pragma unroll
        for (int t = 0; t < 4; t++) {
            int n = ng*4 + t;
            oh[(size_t)sDstN[n]*HID + j] = smf[SM_HD/4 + n*LDD + j] + acc[t];
        }
    }
}

// ---------------- launch ----------------
extern "C" void kernel_launch(void* const* d_in, const int* in_sizes, int n_in,
                              void* d_out, int out_size)
{
    const float* coords = (const float*)d_in[0];
    const float* hidden = (const float*)d_in[1];
    const void*  edges  = d_in[2];
    const float* W1  = (const float*)d_in[3];
    const float* b1  = (const float*)d_in[4];
    const float* W2  = (const float*)d_in[5];
    const float* b2  = (const float*)d_in[6];
    const float* Wa  = (const float*)d_in[7];
    const float* ba  = (const float*)d_in[8];
    const float* Wc1 = (const float*)d_in[9];
    const float* bc1 = (const float*)d_in[10];
    const float* Wc2 = (const float*)d_in[11];
    const float* Wh1 = (const float*)d_in[12];
    const float* bh1 = (const float*)d_in[13];
    const float* Wh2 = (const float*)d_in[14];
    const float* bh2 = (const float*)d_in[15];

    int N = in_sizes[0] / 3;
    float* out = (float*)d_out;

    prep_kernel<<<192, 256>>>(W1, W2, Wc1);
    cudaFuncSetAttribute(egnn_mma_kernel, cudaFuncAttributeMaxDynamicSharedMemorySize,
                         SMEM_BYTES);
    egnn_mma_kernel<<<N / NPC, THREADS, SMEM_BYTES>>>(
        coords, hidden, edges, W1, b1, b2, Wa, ba, bc1, Wc2,
        Wh1, bh1, Wh2, bh2, out, N);
}